// round 12
// baseline (speedup 1.0000x reference)
#include <cuda_runtime.h>
#include <cuda_fp16.h>
#include <stdint.h>

// ---------------- problem sizes ----------------
#define BB 2
#define NN 4096
#define EE 512
#define HH 8
#define DD 64
#define MMR (BB*NN)            // 8192
#define E1  (MMR*EE)           // 4194304

// Q prescale: log2(e)/8, folded into the Q projection epilogue
#define QSCALE 0.18033688011112042f

// ---------------- scratch ----------------
__device__ __align__(256) __half g_scratch[6u*E1];

#define SWZ(o) ((o) ^ (((o) >> 3) & 0x70))

__device__ __forceinline__ uint32_t smem_u32(const void* p) {
    uint32_t a;
    asm("{ .reg .u64 t; cvta.to.shared.u64 t, %1; cvt.u32.u64 %0, t; }" : "=r"(a) : "l"(p));
    return a;
}
__device__ __forceinline__ void mma_f16(float c[4], const uint32_t a[4], const uint32_t b[2]) {
    asm volatile("mma.sync.aligned.m16n8k16.row.col.f32.f16.f16.f32 "
        "{%0,%1,%2,%3}, {%4,%5,%6,%7}, {%8,%9}, {%0,%1,%2,%3};"
        : "+f"(c[0]), "+f"(c[1]), "+f"(c[2]), "+f"(c[3])
        : "r"(a[0]), "r"(a[1]), "r"(a[2]), "r"(a[3]), "r"(b[0]), "r"(b[1]));
}
__device__ __forceinline__ void ldsm4(uint32_t r[4], uint32_t addr) {
    asm volatile("ldmatrix.sync.aligned.m8n8.x4.shared.b16 {%0,%1,%2,%3}, [%4];"
        : "=r"(r[0]), "=r"(r[1]), "=r"(r[2]), "=r"(r[3]) : "r"(addr));
}
__device__ __forceinline__ uint32_t h2ex2(uint32_t x) {
    uint32_t r;
    asm("ex2.approx.f16x2 %0, %1;" : "=r"(r) : "r"(x));
    return r;
}
__device__ __forceinline__ uint32_t hadd2(uint32_t a, uint32_t b) {
    uint32_t r;
    asm("add.f16x2 %0, %1, %2;" : "=r"(r) : "r"(a), "r"(b));
    return r;
}
__device__ __forceinline__ float2 h2f2(uint32_t p) {
    __half2 h = *reinterpret_cast<__half2*>(&p);
    return __half22float2(h);
}
// A-operand x4: 16x16 tile at (rowbase, colByte); rows of 128B, SW128 swizzled
__device__ __forceinline__ uint32_t addrA(uint32_t base, int rowbase, int colByte, int lane) {
    int row = rowbase + (lane & 7) + (lane & 8);
    int col = colByte + ((lane >> 4) << 4);
    uint32_t off = (uint32_t)(row * 128 + col);
    return base + SWZ(off);
}
// B-operand x4: two n-tiles (16 rows) x 16 k-bytes
__device__ __forceinline__ uint32_t addrB(uint32_t base, int nbase, int kByte, int lane) {
    int row = nbase + (lane & 7) + (((lane >> 4) & 1) << 3);
    int col = kByte + (((lane >> 3) & 1) << 4);
    uint32_t off = (uint32_t)(row * 128 + col);
    return base + SWZ(off);
}
__device__ __forceinline__ uint32_t pack_f16(float lo, float hi) {
    uint32_t r;
    asm("cvt.rn.f16x2.f32 %0, %1, %2;" : "=r"(r) : "f"(hi), "f"(lo));
    return r;
}

// ---------------- tile loaders: nrows x 64 cols, SW128 rows of 128B ----------------
template<int NT>
__device__ __forceinline__ void load_tile(const __half* __restrict__ g,
                                          size_t row0, int stride, int k0,
                                          char* sdst, int nrows, int tid)
{
    const int total = nrows * 16;
    for (int i = tid; i < total; i += NT) {
        int r = i >> 4, c = i & 15;
        uint2 v = *reinterpret_cast<const uint2*>(g + (row0 + r) * (size_t)stride + k0 + c * 4);
        *reinterpret_cast<uint2*>(sdst + SWZ((uint32_t)(r * 128 + c * 8))) = v;
    }
}
template<int NT>
__device__ __forceinline__ void load_tile_f32(const float* __restrict__ g,
                                              size_t row0, int stride, int k0,
                                              char* sdst, int nrows, int tid)
{
    const int total = nrows * 16;
    for (int i = tid; i < total; i += NT) {
        int r = i >> 4, c = i & 15;
        float4 f = *reinterpret_cast<const float4*>(g + (row0 + r) * (size_t)stride + k0 + c * 4);
        uint2 v = make_uint2(pack_f16(f.x, f.y), pack_f16(f.z, f.w));
        *reinterpret_cast<uint2*>(sdst + SWZ((uint32_t)(r * 128 + c * 8))) = v;
    }
}

// ---- register prefetch, fp16: 64 rows x 64 cols, 128 threads (attention) ----
__device__ __forceinline__ void pf_ld64s(const __half* __restrict__ g,
                                         size_t row0, int stride, int k0,
                                         uint4 r[4], int tid)
{
#pragma unroll
    for (int i = 0; i < 4; i++) {
        int idx = tid + i * 128;
        int rr = idx >> 3, cc = idx & 7;
        r[i] = *reinterpret_cast<const uint4*>(g + (row0 + rr) * (size_t)stride + k0 + cc * 8);
    }
}
__device__ __forceinline__ void pf_st64s(const uint4 r[4], char* s, int tid)
{
#pragma unroll
    for (int i = 0; i < 4; i++) {
        int idx = tid + i * 128;
        int rr = idx >> 3, cc = idx & 7;
        *reinterpret_cast<uint4*>(s + SWZ((uint32_t)(rr * 128 + cc * 16))) = r[i];
    }
}

// ---- GEMM prefetch (256 threads): fp32 -> fp16x2, 64 rows (8 regs held) ----
__device__ __forceinline__ void pf64fc(const float* __restrict__ g,
                                       size_t row0, int stride, int k0,
                                       uint2 r[4], int tid)
{
#pragma unroll
    for (int i = 0; i < 4; i++) {
        int idx = tid + i * 256;        // 0..1023
        int rr = idx >> 4, cc = idx & 15;
        float4 f = *reinterpret_cast<const float4*>(g + (row0 + rr) * (size_t)stride + k0 + cc * 4);
        r[i] = make_uint2(pack_f16(f.x, f.y), pack_f16(f.z, f.w));
    }
}
__device__ __forceinline__ void pf64fc_st(const uint2 r[4], char* s, int tid)
{
#pragma unroll
    for (int i = 0; i < 4; i++) {
        int idx = tid + i * 256;
        int rr = idx >> 4, cc = idx & 15;
        *reinterpret_cast<uint2*>(s + SWZ((uint32_t)(rr * 128 + cc * 8))) = r[i];
    }
}
// ---- GEMM prefetch (256 threads): fp32 -> fp16x2, 128 rows (16 regs held) ----
__device__ __forceinline__ void pf128fc(const float* __restrict__ g,
                                        size_t row0, int stride, int k0,
                                        uint2 r[8], int tid)
{
#pragma unroll
    for (int i = 0; i < 8; i++) {
        int idx = tid + i * 256;        // 0..2047
        int rr = idx >> 4, cc = idx & 15;
        float4 f = *reinterpret_cast<const float4*>(g + (row0 + rr) * (size_t)stride + k0 + cc * 4);
        r[i] = make_uint2(pack_f16(f.x, f.y), pack_f16(f.z, f.w));
    }
}
__device__ __forceinline__ void pf128fc_st(const uint2 r[8], char* s, int tid)
{
#pragma unroll
    for (int i = 0; i < 8; i++) {
        int idx = tid + i * 256;
        int rr = idx >> 4, cc = idx & 15;
        *reinterpret_cast<uint2*>(s + SWZ((uint32_t)(rr * 128 + cc * 8))) = r[i];
    }
}
// ---- GEMM prefetch (256 threads): fp16 source, 64 rows (8 regs held) ----
__device__ __forceinline__ void pf64h(const __half* __restrict__ g,
                                      size_t row0, int stride, int k0, uint4 r[2], int tid)
{
#pragma unroll
    for (int i = 0; i < 2; i++) {
        int idx = tid + i * 256;        // 0..511
        int rr = idx >> 3, cc = idx & 7;
        r[i] = *reinterpret_cast<const uint4*>(g + (row0 + rr) * (size_t)stride + k0 + cc * 8);
    }
}
__device__ __forceinline__ void pf64h_st(const uint4 r[2], char* s, int tid)
{
#pragma unroll
    for (int i = 0; i < 2; i++) {
        int idx = tid + i * 256;
        int rr = idx >> 3, cc = idx & 7;
        *reinterpret_cast<uint4*>(s + SWZ((uint32_t)(rr * 128 + cc * 16))) = r[i];
    }
}

// ---------------- fused QKV projection: 64x128 tiles, 3 CTAs/SM ----------------
// smem stage: A(64x64 f16, 8KB)@0, B(128x64 f16, 16KB)@8K; two stages = 48KB.
#define G_SMEM 49152
#define G_STG 24576

__global__ void __launch_bounds__(256, 3) gemm_qkv(
    const float* __restrict__ q, const float* __restrict__ k, const float* __restrict__ v,
    const float* __restrict__ Wq, const float* __restrict__ Wk, const float* __restrict__ Wv,
    const float* __restrict__ bq, const float* __restrict__ bk, const float* __restrict__ bv,
    __half* __restrict__ qp, __half* __restrict__ kp, __half* __restrict__ vtp)
{
    extern __shared__ char sm[];
    const int z = blockIdx.z;
    const float* X    = (z == 0) ? q  : (z == 1) ? k  : v;
    const float* W    = (z == 0) ? Wq : (z == 1) ? Wk : Wv;
    const float* bias = (z == 0) ? bq : (z == 1) ? bk : bv;
    __half* Oh        = (z == 0) ? qp : (z == 1) ? kp : vtp;
    const float oscale = (z == 0) ? QSCALE : 1.0f;

    const int tid = threadIdx.x, lane = tid & 31, wid = tid >> 5;
    const int wm = wid & 1, wn = wid >> 1;       // 2 m-slices x 4 n-slices
    const int m0 = blockIdx.y * 64, n0 = blockIdx.x * 128;
    const uint32_t sb = smem_u32(sm);

    load_tile_f32<256>(X, (size_t)m0, EE, 0, sm + 0,    64,  tid);
    load_tile_f32<256>(W, (size_t)n0, EE, 0, sm + 8192, 128, tid);
    __syncthreads();

    float c[2][4][4] = {};

    for (int chunk = 0; chunk < 8; chunk++) {
        const uint32_t cur = (chunk & 1) * G_STG;
        uint2 pa[4], pb[8];
        if (chunk < 7) {
            const int k0 = (chunk + 1) * 64;
            pf64fc (X, (size_t)m0, EE, k0, pa, tid);
            pf128fc(W, (size_t)n0, EE, k0, pb, tid);
        }
#pragma unroll
        for (int kk = 0; kk < 4; kk++) {
            uint32_t af[2][4];
            ldsm4(af[0], addrA(sb + cur + 0, 32*wm,      kk*32, lane));
            ldsm4(af[1], addrA(sb + cur + 0, 32*wm + 16, kk*32, lane));
#pragma unroll
            for (int t = 0; t < 2; t++) {
                uint32_t bh[4];
                ldsm4(bh, addrB(sb + cur + 8192, 32*wn + 16*t, kk*32, lane));
#pragma unroll
                for (int mt = 0; mt < 2; mt++) {
                    mma_f16(c[mt][2*t],   af[mt], bh);
                    mma_f16(c[mt][2*t+1], af[mt], bh + 2);
                }
            }
        }
        if (chunk < 7) {
            const uint32_t oth = ((chunk + 1) & 1) * G_STG;
            pf64fc_st (pa, sm + oth + 0,    tid);
            pf128fc_st(pb, sm + oth + 8192, tid);
        }
        __syncthreads();
    }

    const int g = lane >> 2, tig = lane & 3;
    if (z != 2) {
        // Q/K: [B,H,N,D], half2 stores
#pragma unroll
        for (int mt = 0; mt < 2; mt++) {
#pragma unroll
            for (int t = 0; t < 4; t++) {
                const int e = n0 + 32*wn + 8*t + 2*tig;
                const float bv0 = bias[e], bv1 = bias[e + 1];
#pragma unroll
                for (int hf = 0; hf < 2; hf++) {
                    const int m = m0 + 32*wm + 16*mt + g + 8*hf;
                    const float v0 = (c[mt][t][2*hf] + bv0) * oscale;
                    const float v1 = (c[mt][t][2*hf + 1] + bv1) * oscale;
                    const int bb = m >> 12, nn = m & (NN - 1);
                    const int hh = e >> 6, d = e & 63;
                    size_t idx = (((size_t)bb*HH + hh)*NN + nn)*DD + d;
                    *reinterpret_cast<uint32_t*>(Oh + idx) = pack_f16(v0, v1);
                }
            }
        }
    } else {
        // V: stage through smem, emit coalesced rows of [B,H,D,N]
        __half* st = reinterpret_cast<__half*>(sm);     // [128 e][72 pad] halves
#pragma unroll
        for (int mt = 0; mt < 2; mt++) {
#pragma unroll
            for (int t = 0; t < 4; t++) {
                const int e = 32*wn + 8*t + 2*tig;
                const float bv0 = bias[n0 + e], bv1 = bias[n0 + e + 1];
#pragma unroll
                for (int hf = 0; hf < 2; hf++) {
                    const int ml = 32*wm + 16*mt + g + 8*hf;
                    st[e * 72 + ml]       = __float2half_rn(c[mt][t][2*hf] + bv0);
                    st[(e + 1) * 72 + ml] = __float2half_rn(c[mt][t][2*hf + 1] + bv1);
                }
            }
        }
        __syncthreads();
        const int bb = m0 >> 12;
        const int nbase = m0 & (NN - 1);
#pragma unroll
        for (int j = 0; j < 4; j++) {
            int i = tid + j * 256;          // 0..1023
            int r = i >> 3, cc = i & 7;     // e row, 8-elem chunk
            uint4 val = *reinterpret_cast<const uint4*>(st + r * 72 + cc * 8);
            const int eg = n0 + r;
            const int hh = eg >> 6, d = eg & 63;
            *reinterpret_cast<uint4*>(Oh + (((size_t)bb*HH + hh)*DD + d)*NN + nbase + cc*8) = val;
        }
    }
}

// ---------------- output projection: 64x128 tiles, 3 CTAs/SM ----------------
__global__ void __launch_bounds__(256, 3) gemm_o(
    const __half* __restrict__ A16, const float* __restrict__ W,
    const float* __restrict__ bias, float* __restrict__ Of)
{
    extern __shared__ char sm[];
    const int tid = threadIdx.x, lane = tid & 31, wid = tid >> 5;
    const int wm = wid & 1, wn = wid >> 1;
    const int m0 = blockIdx.y * 64, n0 = blockIdx.x * 128;
    const uint32_t sb = smem_u32(sm);

    load_tile<256>(A16, (size_t)m0, EE, 0, sm + 0,    64,  tid);
    load_tile_f32<256>(W, (size_t)n0, EE, 0, sm + 8192, 128, tid);
    __syncthreads();

    float c[2][4][4] = {};

    for (int chunk = 0; chunk < 8; chunk++) {
        const uint32_t cur = (chunk & 1) * G_STG;
        uint4 pa[2]; uint2 pb[8];
        if (chunk < 7) {
            const int k0 = (chunk + 1) * 64;
            pf64h  (A16, (size_t)m0, EE, k0, pa, tid);
            pf128fc(W,   (size_t)n0, EE, k0, pb, tid);
        }
#pragma unroll
        for (int kk = 0; kk < 4; kk++) {
            uint32_t af[2][4];
            ldsm4(af[0], addrA(sb + cur + 0, 32*wm,      kk*32, lane));
            ldsm4(af[1], addrA(sb + cur + 0, 32*wm + 16, kk*32, lane));
#pragma unroll
            for (int t = 0; t < 2; t++) {
                uint32_t bh[4];
                ldsm4(bh, addrB(sb + cur + 8192, 32*wn + 16*t, kk*32, lane));
#pragma unroll
                for (int mt = 0; mt < 2; mt++) {
                    mma_f16(c[mt][2*t],   af[mt], bh);
                    mma_f16(c[mt][2*t+1], af[mt], bh + 2);
                }
            }
        }
        if (chunk < 7) {
            const uint32_t oth = ((chunk + 1) & 1) * G_STG;
            pf64h_st  (pa, sm + oth + 0,    tid);
            pf128fc_st(pb, sm + oth + 8192, tid);
        }
        __syncthreads();
    }

    const int g = lane >> 2, tig = lane & 3;
#pragma unroll
    for (int mt = 0; mt < 2; mt++) {
#pragma unroll
        for (int t = 0; t < 4; t++) {
            const int e = n0 + 32*wn + 8*t + 2*tig;
            const float bv0 = bias[e], bv1 = bias[e + 1];
#pragma unroll
            for (int hf = 0; hf < 2; hf++) {
                const int m = m0 + 32*wm + 16*mt + g + 8*hf;
                *reinterpret_cast<float2*>(Of + (size_t)m * EE + e) =
                    make_float2(c[mt][t][2*hf] + bv0, c[mt][t][2*hf + 1] + bv1);
            }
        }
    }
}

// ---------------- flash attention: softmax pipelined against S MMAs ----------------
// CTA = 128 q-rows of one (b,h); 4 warps x 32 q-rows; 64-key tiles; 2 CTAs/SM; 1 sync/tile.
#define A_QH 0
#define A_KV0 16384        // stage s at A_KV0 + s*16384: K (8KB) then V (8KB)
#define A_SMEM 49152

__global__ void __launch_bounds__(128, 2) attn_mma(
    const __half* __restrict__ qp, const __half* __restrict__ kp,
    const __half* __restrict__ vt, __half* __restrict__ att)
{
    extern __shared__ char sm[];
    const int tid = threadIdx.x, lane = tid & 31, wid = tid >> 5;
    const int b = blockIdx.z, h = blockIdx.y, i0 = blockIdx.x * 128;
    const int bh = b * HH + h;
    const uint32_t sb = smem_u32(sm);

    load_tile<128>(qp, (size_t)bh * NN + i0, DD, 0, sm + A_QH, 128, tid);
    load_tile<128>(kp, (size_t)bh * NN, DD, 0, sm + A_KV0, 64, tid);
    load_tile<128>(vt, (size_t)bh * DD, NN, 0, sm + A_KV0 + 8192, 64, tid);
    __syncthreads();

    // Q fragments hoisted: constant across all key tiles
    uint32_t qf[4][2][4];
#pragma unroll
    for (int kk = 0; kk < 4; kk++) {
        ldsm4(qf[kk][0], addrA(sb + A_QH, 32*wid,      kk*32, lane));
        ldsm4(qf[kk][1], addrA(sb + A_QH, 32*wid + 16, kk*32, lane));
    }

    float o[2][8][4] = {};
    float lsum[2][2] = {};

    for (int t = 0; t < 64; t++) {
        const uint32_t bK = sb + A_KV0 + (t & 1) * 16384;
        const uint32_t bV = bK + 8192;
        char* nxt = sm + A_KV0 + ((t + 1) & 1) * 16384;

        uint4 kreg[4], vreg[4];
        if (t < 63) {
            pf_ld64s(kp, (size_t)bh * NN + (t + 1) * 64, DD, 0, kreg, tid);
            pf_ld64s(vt, (size_t)bh * DD, NN, (t + 1) * 64, vreg, tid);
        }

        float c[2][8][4] = {};

        // exp + PV for key-slice j (16 keys): runs under S(j+1)'s MMA latency
        auto exp_pv = [&](int j) {
            uint32_t ah[2][4];
#pragma unroll
            for (int mt = 0; mt < 2; mt++) {
                uint32_t a01a = h2ex2(pack_f16(c[mt][2*j][0],   c[mt][2*j][1]));
                uint32_t a23a = h2ex2(pack_f16(c[mt][2*j][2],   c[mt][2*j][3]));
                uint32_t a01b = h2ex2(pack_f16(c[mt][2*j+1][0], c[mt][2*j+1][1]));
                uint32_t a23b = h2ex2(pack_f16(c[mt][2*j+1][2], c[mt][2*j+1][3]));
                ah[mt][0] = a01a; ah[mt][1] = a23a; ah[mt][2] = a01b; ah[mt][3] = a23b;
                float2 f01 = h2f2(hadd2(a01a, a01b));
                float2 f23 = h2f2(hadd2(a23a, a23b));
                lsum[mt][0] += f01.x + f01.y;
                lsum[mt][1] += f23.x + f23.y;
            }
#pragma unroll
            for (int tv = 0; tv < 4; tv++) {
                uint32_t vh[4];
                ldsm4(vh, addrB(bV, 16*tv, j*32, lane));
#pragma unroll
                for (int mt = 0; mt < 2; mt++) {
                    mma_f16(o[mt][2*tv],   ah[mt], vh);
                    mma_f16(o[mt][2*tv+1], ah[mt], vh + 2);
                }
            }
        };

#pragma unroll
        for (int tt = 0; tt < 4; tt++) {
#pragma unroll
            for (int kk = 0; kk < 4; kk++) {
                uint32_t bhf[4];
                ldsm4(bhf, addrB(bK, 16*tt, kk*32, lane));
#pragma unroll
                for (int mt = 0; mt < 2; mt++) {
                    mma_f16(c[mt][2*tt],   qf[kk][mt], bhf);
                    mma_f16(c[mt][2*tt+1], qf[kk][mt], bhf + 2);
                }
            }
            if (tt > 0) exp_pv(tt - 1);
        }
        exp_pv(3);

        if (t < 63) {
            pf_st64s(kreg, nxt, tid);
            pf_st64s(vreg, nxt + 8192, tid);
        }
        __syncthreads();
    }

    // ---- reduce row sums across the 4 tig lanes, normalize, write fp16 ----
#pragma unroll
    for (int mt = 0; mt < 2; mt++)
#pragma unroll
        for (int hf = 0; hf < 2; hf++) {
            float s = lsum[mt][hf];
            s += __shfl_xor_sync(0xffffffffu, s, 1);
            s += __shfl_xor_sync(0xffffffffu, s, 2);
            lsum[mt][hf] = 1.0f / s;
        }

    const int g = lane >> 2, tig = lane & 3;
#pragma unroll
    for (int mt = 0; mt < 2; mt++) {
#pragma unroll
        for (int nt = 0; nt < 8; nt++) {
            const int d = 8*nt + 2*tig;
#pragma unroll
            for (int hf = 0; hf < 2; hf++) {
                const float inv = lsum[mt][hf];
                const int row = i0 + 32*wid + 16*mt + g + 8*hf;
                const size_t idx = ((size_t)b * NN + row) * EE + h * DD + d;
                *reinterpret_cast<uint32_t*>(att + idx) =
                    pack_f16(o[mt][nt][2*hf] * inv, o[mt][nt][2*hf + 1] * inv);
            }
        }
    }
}

// ---------------- host ----------------
extern "C" void kernel_launch(void* const* d_in, const int* in_sizes, int n_in,
                              void* d_out, int out_size)
{
    const float* q  = (const float*)d_in[0];
    const float* k  = (const float*)d_in[1];
    const float* v  = (const float*)d_in[2];
    const float* Wq = (const float*)d_in[3];
    const float* bq = (const float*)d_in[4];
    const float* Wk = (const float*)d_in[5];
    const float* bk = (const float*)d_in[6];
    const float* Wv = (const float*)d_in[7];
    const float* bv = (const float*)d_in[8];
    const float* Wo = (const float*)d_in[9];
    const float* bo = (const float*)d_in[10];
    float* out = (float*)d_out;

    __half* s;
    cudaGetSymbolAddress((void**)&s, g_scratch);
    __half *qp  = s,
           *kp  = s + (size_t)E1,
           *vtp = s + 2*(size_t)E1,
           *att = s + 3*(size_t)E1;

    cudaFuncSetAttribute(gemm_qkv, cudaFuncAttributeMaxDynamicSharedMemorySize, G_SMEM);
    cudaFuncSetAttribute(gemm_o,   cudaFuncAttributeMaxDynamicSharedMemorySize, G_SMEM);
    cudaFuncSetAttribute(attn_mma, cudaFuncAttributeMaxDynamicSharedMemorySize, A_SMEM);

    gemm_qkv<<<dim3(EE/128, MMR/64, 3), 256, G_SMEM>>>(
        q, k, v, Wq, Wk, Wv, bq, bk, bv, qp, kp, vtp);

    attn_mma<<<dim3(NN/128, HH, BB), 128, A_SMEM>>>(qp, kp, vtp, att);

    gemm_o<<<dim3(EE/128, MMR/64), 256, G_SMEM>>>(att, Wo, bo, out);
}

// round 13
// speedup vs baseline: 1.0260x; 1.0260x over previous
#include <cuda_runtime.h>
#include <cuda_fp16.h>
#include <stdint.h>

// ---------------- problem sizes ----------------
#define BB 2
#define NN 4096
#define EE 512
#define HH 8
#define DD 64
#define MMR (BB*NN)            // 8192
#define E1  (MMR*EE)           // 4194304

// Q prescale: log2(e)/8, folded into the Q projection epilogue
#define QSCALE 0.18033688011112042f

// ---------------- scratch ----------------
__device__ __align__(256) __half g_scratch[6u*E1];

#define SWZ(o) ((o) ^ (((o) >> 3) & 0x70))

__device__ __forceinline__ uint32_t smem_u32(const void* p) {
    uint32_t a;
    asm("{ .reg .u64 t; cvta.to.shared.u64 t, %1; cvt.u32.u64 %0, t; }" : "=r"(a) : "l"(p));
    return a;
}
__device__ __forceinline__ void mma_f16(float c[4], const uint32_t a[4], const uint32_t b[2]) {
    asm volatile("mma.sync.aligned.m16n8k16.row.col.f32.f16.f16.f32 "
        "{%0,%1,%2,%3}, {%4,%5,%6,%7}, {%8,%9}, {%0,%1,%2,%3};"
        : "+f"(c[0]), "+f"(c[1]), "+f"(c[2]), "+f"(c[3])
        : "r"(a[0]), "r"(a[1]), "r"(a[2]), "r"(a[3]), "r"(b[0]), "r"(b[1]));
}
__device__ __forceinline__ void ldsm4(uint32_t r[4], uint32_t addr) {
    asm volatile("ldmatrix.sync.aligned.m8n8.x4.shared.b16 {%0,%1,%2,%3}, [%4];"
        : "=r"(r[0]), "=r"(r[1]), "=r"(r[2]), "=r"(r[3]) : "r"(addr));
}
__device__ __forceinline__ uint32_t h2ex2(uint32_t x) {
    uint32_t r;
    asm("ex2.approx.f16x2 %0, %1;" : "=r"(r) : "r"(x));
    return r;
}
__device__ __forceinline__ uint32_t hadd2(uint32_t a, uint32_t b) {
    uint32_t r;
    asm("add.f16x2 %0, %1, %2;" : "=r"(r) : "r"(a), "r"(b));
    return r;
}
__device__ __forceinline__ float2 h2f2(uint32_t p) {
    __half2 h = *reinterpret_cast<__half2*>(&p);
    return __half22float2(h);
}
// A-operand x4: 16x16 tile at (rowbase, colByte); rows of 128B, SW128 swizzled
__device__ __forceinline__ uint32_t addrA(uint32_t base, int rowbase, int colByte, int lane) {
    int row = rowbase + (lane & 7) + (lane & 8);
    int col = colByte + ((lane >> 4) << 4);
    uint32_t off = (uint32_t)(row * 128 + col);
    return base + SWZ(off);
}
// B-operand x4: two n-tiles (16 rows) x 16 k-bytes
__device__ __forceinline__ uint32_t addrB(uint32_t base, int nbase, int kByte, int lane) {
    int row = nbase + (lane & 7) + (((lane >> 4) & 1) << 3);
    int col = kByte + (((lane >> 3) & 1) << 4);
    uint32_t off = (uint32_t)(row * 128 + col);
    return base + SWZ(off);
}
__device__ __forceinline__ uint32_t pack_f16(float lo, float hi) {
    uint32_t r;
    asm("cvt.rn.f16x2.f32 %0, %1, %2;" : "=r"(r) : "f"(hi), "f"(lo));
    return r;
}

// ---------------- tile loaders: nrows x 64 cols, SW128 rows of 128B ----------------
template<int NT>
__device__ __forceinline__ void load_tile(const __half* __restrict__ g,
                                          size_t row0, int stride, int k0,
                                          char* sdst, int nrows, int tid)
{
    const int total = nrows * 16;
    for (int i = tid; i < total; i += NT) {
        int r = i >> 4, c = i & 15;
        uint2 v = *reinterpret_cast<const uint2*>(g + (row0 + r) * (size_t)stride + k0 + c * 4);
        *reinterpret_cast<uint2*>(sdst + SWZ((uint32_t)(r * 128 + c * 8))) = v;
    }
}
template<int NT>
__device__ __forceinline__ void load_tile_f32(const float* __restrict__ g,
                                              size_t row0, int stride, int k0,
                                              char* sdst, int nrows, int tid)
{
    const int total = nrows * 16;
    for (int i = tid; i < total; i += NT) {
        int r = i >> 4, c = i & 15;
        float4 f = *reinterpret_cast<const float4*>(g + (row0 + r) * (size_t)stride + k0 + c * 4);
        uint2 v = make_uint2(pack_f16(f.x, f.y), pack_f16(f.z, f.w));
        *reinterpret_cast<uint2*>(sdst + SWZ((uint32_t)(r * 128 + c * 8))) = v;
    }
}

// ---- register prefetch, fp16: 64 rows x 64 cols, 128 threads (attention) ----
__device__ __forceinline__ void pf_ld64s(const __half* __restrict__ g,
                                         size_t row0, int stride, int k0,
                                         uint4 r[4], int tid)
{
#pragma unroll
    for (int i = 0; i < 4; i++) {
        int idx = tid + i * 128;
        int rr = idx >> 3, cc = idx & 7;
        r[i] = *reinterpret_cast<const uint4*>(g + (row0 + rr) * (size_t)stride + k0 + cc * 8);
    }
}
__device__ __forceinline__ void pf_st64s(const uint4 r[4], char* s, int tid)
{
#pragma unroll
    for (int i = 0; i < 4; i++) {
        int idx = tid + i * 128;
        int rr = idx >> 3, cc = idx & 7;
        *reinterpret_cast<uint4*>(s + SWZ((uint32_t)(rr * 128 + cc * 16))) = r[i];
    }
}

// ---- GEMM register prefetch (256 threads), convert-at-load fp32 -> fp16x2 (16 regs) ----
__device__ __forceinline__ void pf_ld128fc(const float* __restrict__ g,
                                           size_t row0, int stride, int k0,
                                           uint2 r[8], int tid)
{
#pragma unroll
    for (int i = 0; i < 8; i++) {
        int idx = tid + i * 256;        // 0..2047
        int rr = idx >> 4, cc = idx & 15;
        float4 f = *reinterpret_cast<const float4*>(g + (row0 + rr) * (size_t)stride + k0 + cc * 4);
        r[i] = make_uint2(pack_f16(f.x, f.y), pack_f16(f.z, f.w));
    }
}
__device__ __forceinline__ void pf_st128c(const uint2 r[8], char* s, int tid)
{
#pragma unroll
    for (int i = 0; i < 8; i++) {
        int idx = tid + i * 256;
        int rr = idx >> 4, cc = idx & 15;
        *reinterpret_cast<uint2*>(s + SWZ((uint32_t)(rr * 128 + cc * 8))) = r[i];
    }
}
// ---- GEMM register prefetch (256 threads), fp16 source (16 regs) ----
__device__ __forceinline__ void pf_ld128h(const __half* __restrict__ g,
                                          size_t row0, int stride, int k0, uint4 r[4], int tid)
{
#pragma unroll
    for (int i = 0; i < 4; i++) {
        int idx = tid + i * 256;
        int rr = idx >> 3, cc = idx & 7;
        r[i] = *reinterpret_cast<const uint4*>(g + (row0 + rr) * (size_t)stride + k0 + cc * 8);
    }
}
__device__ __forceinline__ void pf_st128h(const uint4 r[4], char* s, int tid)
{
#pragma unroll
    for (int i = 0; i < 4; i++) {
        int idx = tid + i * 256;
        int rr = idx >> 3, cc = idx & 7;
        *reinterpret_cast<uint4*>(s + SWZ((uint32_t)(rr * 128 + cc * 16))) = r[i];
    }
}

// ---------------- fused QKV projection, 128x128 tiles, double-buffered, 1 sync/chunk ----------------
// smem: A0@0, B0@16K, A1@32K, B1@48K  (64KB/CTA, 2 CTAs/SM)
#define G_SMEM 65536

__global__ void __launch_bounds__(256, 2) gemm_qkv(
    const float* __restrict__ q, const float* __restrict__ k, const float* __restrict__ v,
    const float* __restrict__ Wq, const float* __restrict__ Wk, const float* __restrict__ Wv,
    const float* __restrict__ bq, const float* __restrict__ bk, const float* __restrict__ bv,
    __half* __restrict__ qp, __half* __restrict__ kp, __half* __restrict__ vtp)
{
    extern __shared__ char sm[];
    const int z = blockIdx.z;
    const float* X    = (z == 0) ? q  : (z == 1) ? k  : v;
    const float* W    = (z == 0) ? Wq : (z == 1) ? Wk : Wv;
    const float* bias = (z == 0) ? bq : (z == 1) ? bk : bv;
    __half* Oh        = (z == 0) ? qp : (z == 1) ? kp : vtp;
    const float oscale = (z == 0) ? QSCALE : 1.0f;

    const int tid = threadIdx.x, lane = tid & 31, wid = tid >> 5;
    const int wm = wid & 3, wn = wid >> 2;
    const int m0 = blockIdx.y * 128, n0 = blockIdx.x * 128;
    const uint32_t sb = smem_u32(sm);

    load_tile_f32<256>(X, (size_t)m0, EE, 0, sm + 0,     128, tid);
    load_tile_f32<256>(W, (size_t)n0, EE, 0, sm + 16384, 128, tid);
    __syncthreads();

    float c[2][8][4] = {};

    for (int chunk = 0; chunk < 8; chunk++) {
        const uint32_t cur = (chunk & 1) * 32768;
        uint2 pa[8], pb[8];
        if (chunk < 7) {
            const int k0 = (chunk + 1) * 64;
            pf_ld128fc(X, (size_t)m0, EE, k0, pa, tid);
            pf_ld128fc(W, (size_t)n0, EE, k0, pb, tid);
        }
#pragma unroll
        for (int kk = 0; kk < 4; kk++) {
            uint32_t af[2][4];
            ldsm4(af[0], addrA(sb + cur + 0, 32*wm,      kk*32, lane));
            ldsm4(af[1], addrA(sb + cur + 0, 32*wm + 16, kk*32, lane));
#pragma unroll
            for (int t = 0; t < 4; t++) {
                uint32_t bh[4];
                ldsm4(bh, addrB(sb + cur + 16384, 64*wn + 16*t, kk*32, lane));
#pragma unroll
                for (int mt = 0; mt < 2; mt++) {
                    mma_f16(c[mt][2*t],   af[mt], bh);
                    mma_f16(c[mt][2*t+1], af[mt], bh + 2);
                }
            }
        }
        if (chunk < 7) {
            const uint32_t oth = ((chunk + 1) & 1) * 32768;
            pf_st128c(pa, sm + oth + 0,     tid);
            pf_st128c(pb, sm + oth + 16384, tid);
        }
        __syncthreads();
    }

    const int g = lane >> 2, tig = lane & 3;
    if (z != 2) {
        // Q/K: [B,H,N,D], half2 stores (coalesced within 32B)
#pragma unroll
        for (int mt = 0; mt < 2; mt++) {
#pragma unroll
            for (int t = 0; t < 8; t++) {
                const int e = n0 + 64*wn + 8*t + 2*tig;
                const float bv0 = bias[e], bv1 = bias[e + 1];
#pragma unroll
                for (int hf = 0; hf < 2; hf++) {
                    const int m = m0 + 32*wm + 16*mt + g + 8*hf;
                    const float v0 = (c[mt][t][2*hf] + bv0) * oscale;
                    const float v1 = (c[mt][t][2*hf + 1] + bv1) * oscale;
                    const int bb = m >> 12, nn = m & (NN - 1);
                    const int hh = e >> 6, d = e & 63;
                    size_t idx = (((size_t)bb*HH + hh)*NN + nn)*DD + d;
                    *reinterpret_cast<uint32_t*>(Oh + idx) = pack_f16(v0, v1);
                }
            }
        }
    } else {
        // V: stage through smem (free after mainloop), emit coalesced [B,H,D,N] rows
        __half* st = reinterpret_cast<__half*>(sm);     // [128 e][136 pad] halves = 34.8KB
#pragma unroll
        for (int mt = 0; mt < 2; mt++) {
#pragma unroll
            for (int t = 0; t < 8; t++) {
                const int el = 64*wn + 8*t + 2*tig;
                const float bv0 = bias[n0 + el], bv1 = bias[n0 + el + 1];
#pragma unroll
                for (int hf = 0; hf < 2; hf++) {
                    const int ml = 32*wm + 16*mt + g + 8*hf;
                    st[el * 136 + ml]       = __float2half_rn(c[mt][t][2*hf] + bv0);
                    st[(el + 1) * 136 + ml] = __float2half_rn(c[mt][t][2*hf + 1] + bv1);
                }
            }
        }
        __syncthreads();
        const int bb = m0 >> 12;
        const int nbase = m0 & (NN - 1);
#pragma unroll
        for (int j = 0; j < 8; j++) {
            int i = tid + j * 256;          // 0..2047
            int r = i >> 4, cc = i & 15;    // e row, 8-half chunk
            uint4 val = *reinterpret_cast<const uint4*>(st + r * 136 + cc * 8);
            const int eg = n0 + r;
            const int hh = eg >> 6, d = eg & 63;
            *reinterpret_cast<uint4*>(Oh + (((size_t)bb*HH + hh)*DD + d)*NN + nbase + cc*8) = val;
        }
    }
}

// ---------------- output projection, 128x128 tiles, double-buffered, 1 sync/chunk ----------------
__global__ void __launch_bounds__(256, 2) gemm_o(
    const __half* __restrict__ A16, const float* __restrict__ W,
    const float* __restrict__ bias, float* __restrict__ Of)
{
    extern __shared__ char sm[];
    const int tid = threadIdx.x, lane = tid & 31, wid = tid >> 5;
    const int wm = wid & 3, wn = wid >> 2;
    const int m0 = blockIdx.y * 128, n0 = blockIdx.x * 128;
    const uint32_t sb = smem_u32(sm);

    load_tile<256>(A16, (size_t)m0, EE, 0, sm + 0,     128, tid);
    load_tile_f32<256>(W, (size_t)n0, EE, 0, sm + 16384, 128, tid);
    __syncthreads();

    float c[2][8][4] = {};

    for (int chunk = 0; chunk < 8; chunk++) {
        const uint32_t cur = (chunk & 1) * 32768;
        uint4 pa[4]; uint2 pb[8];
        if (chunk < 7) {
            const int k0 = (chunk + 1) * 64;
            pf_ld128h(A16, (size_t)m0, EE, k0, pa, tid);
            pf_ld128fc(W, (size_t)n0, EE, k0, pb, tid);
        }
#pragma unroll
        for (int kk = 0; kk < 4; kk++) {
            uint32_t af[2][4];
            ldsm4(af[0], addrA(sb + cur + 0, 32*wm,      kk*32, lane));
            ldsm4(af[1], addrA(sb + cur + 0, 32*wm + 16, kk*32, lane));
#pragma unroll
            for (int t = 0; t < 4; t++) {
                uint32_t bh[4];
                ldsm4(bh, addrB(sb + cur + 16384, 64*wn + 16*t, kk*32, lane));
#pragma unroll
                for (int mt = 0; mt < 2; mt++) {
                    mma_f16(c[mt][2*t],   af[mt], bh);
                    mma_f16(c[mt][2*t+1], af[mt], bh + 2);
                }
            }
        }
        if (chunk < 7) {
            const uint32_t oth = ((chunk + 1) & 1) * 32768;
            pf_st128h(pa, sm + oth + 0,     tid);
            pf_st128c(pb, sm + oth + 16384, tid);
        }
        __syncthreads();
    }

    const int g = lane >> 2, tig = lane & 3;
#pragma unroll
    for (int mt = 0; mt < 2; mt++) {
#pragma unroll
        for (int t = 0; t < 8; t++) {
            const int e = n0 + 64*wn + 8*t + 2*tig;
            const float bv0 = bias[e], bv1 = bias[e + 1];
#pragma unroll
            for (int hf = 0; hf < 2; hf++) {
                const int m = m0 + 32*wm + 16*mt + g + 8*hf;
                *reinterpret_cast<float2*>(Of + (size_t)m * EE + e) =
                    make_float2(c[mt][t][2*hf] + bv0, c[mt][t][2*hf + 1] + bv1);
            }
        }
    }
}

// ---------------- flash attention: 64 q-row CTAs, 4 CTAs/SM, pipelined softmax ----------------
// CTA = 64 q-rows of one (b,h); 4 warps x 16 q-rows; 64-key tiles; 1 sync/tile.
// K/V register prefetch split so peak prefetch regs = 16.
#define A_QH 0
#define A_KV0 8192         // stage s at A_KV0 + s*16384: K (8KB) then V (8KB)
#define A_SMEM 40960

__global__ void __launch_bounds__(128, 4) attn_mma(
    const __half* __restrict__ qp, const __half* __restrict__ kp,
    const __half* __restrict__ vt, __half* __restrict__ att)
{
    extern __shared__ char sm[];
    const int tid = threadIdx.x, lane = tid & 31, wid = tid >> 5;
    const int b = blockIdx.z, h = blockIdx.y, i0 = blockIdx.x * 64;
    const int bh = b * HH + h;
    const uint32_t sb = smem_u32(sm);

    load_tile<128>(qp, (size_t)bh * NN + i0, DD, 0, sm + A_QH, 64, tid);
    load_tile<128>(kp, (size_t)bh * NN, DD, 0, sm + A_KV0, 64, tid);
    load_tile<128>(vt, (size_t)bh * DD, NN, 0, sm + A_KV0 + 8192, 64, tid);
    __syncthreads();

    // Q fragments hoisted: 16 rows/warp, constant across all key tiles
    uint32_t qf[4][4];
#pragma unroll
    for (int kk = 0; kk < 4; kk++)
        ldsm4(qf[kk], addrA(sb + A_QH, 16*wid, kk*32, lane));

    float o[8][4] = {};
    float lsum[2] = {};

    for (int t = 0; t < 64; t++) {
        const uint32_t bK = sb + A_KV0 + (t & 1) * 16384;
        const uint32_t bV = bK + 8192;
        char* nxt = sm + A_KV0 + ((t + 1) & 1) * 16384;

        uint4 pr[4];                             // shared K-then-V prefetch regs
        if (t < 63)
            pf_ld64s(kp, (size_t)bh * NN + (t + 1) * 64, DD, 0, pr, tid);

        float c[8][4] = {};

        // exp + PV for key-slice j (16 keys): runs under S(j+1)'s MMA latency
        auto exp_pv = [&](int j) {
            uint32_t a01a = h2ex2(pack_f16(c[2*j][0],   c[2*j][1]));
            uint32_t a23a = h2ex2(pack_f16(c[2*j][2],   c[2*j][3]));
            uint32_t a01b = h2ex2(pack_f16(c[2*j+1][0], c[2*j+1][1]));
            uint32_t a23b = h2ex2(pack_f16(c[2*j+1][2], c[2*j+1][3]));
            uint32_t ah[4] = { a01a, a23a, a01b, a23b };
            float2 f01 = h2f2(hadd2(a01a, a01b));
            float2 f23 = h2f2(hadd2(a23a, a23b));
            lsum[0] += f01.x + f01.y;
            lsum[1] += f23.x + f23.y;
#pragma unroll
            for (int tv = 0; tv < 4; tv++) {
                uint32_t vh[4];
                ldsm4(vh, addrB(bV, 16*tv, j*32, lane));
                mma_f16(o[2*tv],   ah, vh);
                mma_f16(o[2*tv+1], ah, vh + 2);
            }
        };

#pragma unroll
        for (int tt = 0; tt < 4; tt++) {
#pragma unroll
            for (int kk = 0; kk < 4; kk++) {
                uint32_t bhf[4];
                ldsm4(bhf, addrB(bK, 16*tt, kk*32, lane));
                mma_f16(c[2*tt],   qf[kk], bhf);
                mma_f16(c[2*tt+1], qf[kk], bhf + 2);
            }
            if (tt > 0) exp_pv(tt - 1);
        }

        if (t < 63) {
            pf_st64s(pr, nxt, tid);              // publish K(t+1)
            pf_ld64s(vt, (size_t)bh * DD, NN, (t + 1) * 64, pr, tid);   // V(t+1)
        }
        exp_pv(3);
        if (t < 63)
            pf_st64s(pr, nxt + 8192, tid);       // publish V(t+1)
        __syncthreads();
    }

    // ---- reduce row sums across the 4 tig lanes, normalize, write fp16 ----
#pragma unroll
    for (int hf = 0; hf < 2; hf++) {
        float s = lsum[hf];
        s += __shfl_xor_sync(0xffffffffu, s, 1);
        s += __shfl_xor_sync(0xffffffffu, s, 2);
        lsum[hf] = 1.0f / s;
    }

    const int g = lane >> 2, tig = lane & 3;
#pragma unroll
    for (int nt = 0; nt < 8; nt++) {
        const int d = 8*nt + 2*tig;
#pragma unroll
        for (int hf = 0; hf < 2; hf++) {
            const float inv = lsum[hf];
            const int row = i0 + 16*wid + g + 8*hf;
            const size_t idx = ((size_t)b * NN + row) * EE + h * DD + d;
            *reinterpret_cast<uint32_t*>(att + idx) =
                pack_f16(o[nt][2*hf] * inv, o[nt][2*hf + 1] * inv);
        }
    }
}

// ---------------- host ----------------
extern "C" void kernel_launch(void* const* d_in, const int* in_sizes, int n_in,
                              void* d_out, int out_size)
{
    const float* q  = (const float*)d_in[0];
    const float* k  = (const float*)d_in[1];
    const float* v  = (const float*)d_in[2];
    const float* Wq = (const float*)d_in[3];
    const float* bq = (const float*)d_in[4];
    const float* Wk = (const float*)d_in[5];
    const float* bk = (const float*)d_in[6];
    const float* Wv = (const float*)d_in[7];
    const float* bv = (const float*)d_in[8];
    const float* Wo = (const float*)d_in[9];
    const float* bo = (const float*)d_in[10];
    float* out = (float*)d_out;

    __half* s;
    cudaGetSymbolAddress((void**)&s, g_scratch);
    __half *qp  = s,
           *kp  = s + (size_t)E1,
           *vtp = s + 2*(size_t)E1,
           *att = s + 3*(size_t)E1;

    cudaFuncSetAttribute(gemm_qkv, cudaFuncAttributeMaxDynamicSharedMemorySize, G_SMEM);
    cudaFuncSetAttribute(gemm_o,   cudaFuncAttributeMaxDynamicSharedMemorySize, G_SMEM);
    cudaFuncSetAttribute(attn_mma, cudaFuncAttributeMaxDynamicSharedMemorySize, A_SMEM);

    gemm_qkv<<<dim3(EE/128, MMR/128, 3), 256, G_SMEM>>>(
        q, k, v, Wq, Wk, Wv, bq, bk, bv, qp, kp, vtp);

    attn_mma<<<dim3(NN/64, HH, BB), 128, A_SMEM>>>(qp, kp, vtp, att);

    gemm_o<<<dim3(EE/128, MMR/128), 256, G_SMEM>>>(att, Wo, bo, out);
}

// round 14
// speedup vs baseline: 1.0805x; 1.0531x over previous
#include <cuda_runtime.h>
#include <cuda_fp16.h>
#include <stdint.h>

// ---------------- problem sizes ----------------
#define BB 2
#define NN 4096
#define EE 512
#define HH 8
#define DD 64
#define MMR (BB*NN)            // 8192
#define E1  (MMR*EE)           // 4194304

// Q prescale: log2(e)/8, folded into the Q projection epilogue
#define QSCALE 0.18033688011112042f

// ---------------- scratch ----------------
__device__ __align__(256) __half g_scratch[6u*E1];

#define SWZ(o) ((o) ^ (((o) >> 3) & 0x70))

__device__ __forceinline__ uint32_t smem_u32(const void* p) {
    uint32_t a;
    asm("{ .reg .u64 t; cvta.to.shared.u64 t, %1; cvt.u32.u64 %0, t; }" : "=r"(a) : "l"(p));
    return a;
}
__device__ __forceinline__ void mma_f16(float c[4], const uint32_t a[4], const uint32_t b[2]) {
    asm volatile("mma.sync.aligned.m16n8k16.row.col.f32.f16.f16.f32 "
        "{%0,%1,%2,%3}, {%4,%5,%6,%7}, {%8,%9}, {%0,%1,%2,%3};"
        : "+f"(c[0]), "+f"(c[1]), "+f"(c[2]), "+f"(c[3])
        : "r"(a[0]), "r"(a[1]), "r"(a[2]), "r"(a[3]), "r"(b[0]), "r"(b[1]));
}
__device__ __forceinline__ void ldsm4(uint32_t r[4], uint32_t addr) {
    asm volatile("ldmatrix.sync.aligned.m8n8.x4.shared.b16 {%0,%1,%2,%3}, [%4];"
        : "=r"(r[0]), "=r"(r[1]), "=r"(r[2]), "=r"(r[3]) : "r"(addr));
}
__device__ __forceinline__ uint32_t h2ex2(uint32_t x) {
    uint32_t r;
    asm("ex2.approx.f16x2 %0, %1;" : "=r"(r) : "r"(x));
    return r;
}
__device__ __forceinline__ uint32_t hadd2(uint32_t a, uint32_t b) {
    uint32_t r;
    asm("add.f16x2 %0, %1, %2;" : "=r"(r) : "r"(a), "r"(b));
    return r;
}
__device__ __forceinline__ float2 h2f2(uint32_t p) {
    __half2 h = *reinterpret_cast<__half2*>(&p);
    return __half22float2(h);
}
// A-operand x4: 16x16 tile at (rowbase, colByte); rows of 128B, SW128 swizzled
__device__ __forceinline__ uint32_t addrA(uint32_t base, int rowbase, int colByte, int lane) {
    int row = rowbase + (lane & 7) + (lane & 8);
    int col = colByte + ((lane >> 4) << 4);
    uint32_t off = (uint32_t)(row * 128 + col);
    return base + SWZ(off);
}
// B-operand x4: two n-tiles (16 rows) x 16 k-bytes
__device__ __forceinline__ uint32_t addrB(uint32_t base, int nbase, int kByte, int lane) {
    int row = nbase + (lane & 7) + (((lane >> 4) & 1) << 3);
    int col = kByte + (((lane >> 3) & 1) << 4);
    uint32_t off = (uint32_t)(row * 128 + col);
    return base + SWZ(off);
}
__device__ __forceinline__ uint32_t pack_f16(float lo, float hi) {
    uint32_t r;
    asm("cvt.rn.f16x2.f32 %0, %1, %2;" : "=r"(r) : "f"(hi), "f"(lo));
    return r;
}

// ---------------- tile loaders: nrows x 64 cols, SW128 rows of 128B ----------------
template<int NT>
__device__ __forceinline__ void load_tile(const __half* __restrict__ g,
                                          size_t row0, int stride, int k0,
                                          char* sdst, int nrows, int tid)
{
    const int total = nrows * 16;
    for (int i = tid; i < total; i += NT) {
        int r = i >> 4, c = i & 15;
        uint2 v = *reinterpret_cast<const uint2*>(g + (row0 + r) * (size_t)stride + k0 + c * 4);
        *reinterpret_cast<uint2*>(sdst + SWZ((uint32_t)(r * 128 + c * 8))) = v;
    }
}
template<int NT>
__device__ __forceinline__ void load_tile_f32(const float* __restrict__ g,
                                              size_t row0, int stride, int k0,
                                              char* sdst, int nrows, int tid)
{
    const int total = nrows * 16;
    for (int i = tid; i < total; i += NT) {
        int r = i >> 4, c = i & 15;
        float4 f = *reinterpret_cast<const float4*>(g + (row0 + r) * (size_t)stride + k0 + c * 4);
        uint2 v = make_uint2(pack_f16(f.x, f.y), pack_f16(f.z, f.w));
        *reinterpret_cast<uint2*>(sdst + SWZ((uint32_t)(r * 128 + c * 8))) = v;
    }
}

// ---- register prefetch, fp16: 64 rows x 64 cols, 128 threads (attention) ----
__device__ __forceinline__ void pf_ld64s(const __half* __restrict__ g,
                                         size_t row0, int stride, int k0,
                                         uint4 r[4], int tid)
{
#pragma unroll
    for (int i = 0; i < 4; i++) {
        int idx = tid + i * 128;
        int rr = idx >> 3, cc = idx & 7;
        r[i] = *reinterpret_cast<const uint4*>(g + (row0 + rr) * (size_t)stride + k0 + cc * 8);
    }
}
__device__ __forceinline__ void pf_st64s(const uint4 r[4], char* s, int tid)
{
#pragma unroll
    for (int i = 0; i < 4; i++) {
        int idx = tid + i * 128;
        int rr = idx >> 3, cc = idx & 7;
        *reinterpret_cast<uint4*>(s + SWZ((uint32_t)(rr * 128 + cc * 16))) = r[i];
    }
}

// ---- GEMM register prefetch (256 threads), convert-at-load fp32 -> fp16x2 (16 regs) ----
__device__ __forceinline__ void pf_ld128fc(const float* __restrict__ g,
                                           size_t row0, int stride, int k0,
                                           uint2 r[8], int tid)
{
#pragma unroll
    for (int i = 0; i < 8; i++) {
        int idx = tid + i * 256;        // 0..2047
        int rr = idx >> 4, cc = idx & 15;
        float4 f = *reinterpret_cast<const float4*>(g + (row0 + rr) * (size_t)stride + k0 + cc * 4);
        r[i] = make_uint2(pack_f16(f.x, f.y), pack_f16(f.z, f.w));
    }
}
__device__ __forceinline__ void pf_st128c(const uint2 r[8], char* s, int tid)
{
#pragma unroll
    for (int i = 0; i < 8; i++) {
        int idx = tid + i * 256;
        int rr = idx >> 4, cc = idx & 15;
        *reinterpret_cast<uint2*>(s + SWZ((uint32_t)(rr * 128 + cc * 8))) = r[i];
    }
}
// ---- GEMM register prefetch (256 threads), fp16 source (16 regs) ----
__device__ __forceinline__ void pf_ld128h(const __half* __restrict__ g,
                                          size_t row0, int stride, int k0, uint4 r[4], int tid)
{
#pragma unroll
    for (int i = 0; i < 4; i++) {
        int idx = tid + i * 256;
        int rr = idx >> 3, cc = idx & 7;
        r[i] = *reinterpret_cast<const uint4*>(g + (row0 + rr) * (size_t)stride + k0 + cc * 8);
    }
}
__device__ __forceinline__ void pf_st128h(const uint4 r[4], char* s, int tid)
{
#pragma unroll
    for (int i = 0; i < 4; i++) {
        int idx = tid + i * 256;
        int rr = idx >> 3, cc = idx & 7;
        *reinterpret_cast<uint4*>(s + SWZ((uint32_t)(rr * 128 + cc * 16))) = r[i];
    }
}

// ---------------- fused QKV projection, 128x128 tiles, double-buffered, 1 sync/chunk ----------------
// smem: A0@0, B0@16K, A1@32K, B1@48K  (64KB/CTA, 2 CTAs/SM)
#define G_SMEM 65536

__global__ void __launch_bounds__(256, 2) gemm_qkv(
    const float* __restrict__ q, const float* __restrict__ k, const float* __restrict__ v,
    const float* __restrict__ Wq, const float* __restrict__ Wk, const float* __restrict__ Wv,
    const float* __restrict__ bq, const float* __restrict__ bk, const float* __restrict__ bv,
    __half* __restrict__ qp, __half* __restrict__ kp, __half* __restrict__ vtp)
{
    extern __shared__ char sm[];
    const int z = blockIdx.z;
    const float* X    = (z == 0) ? q  : (z == 1) ? k  : v;
    const float* W    = (z == 0) ? Wq : (z == 1) ? Wk : Wv;
    const float* bias = (z == 0) ? bq : (z == 1) ? bk : bv;
    __half* Oh        = (z == 0) ? qp : (z == 1) ? kp : vtp;
    const float oscale = (z == 0) ? QSCALE : 1.0f;

    const int tid = threadIdx.x, lane = tid & 31, wid = tid >> 5;
    const int wm = wid & 3, wn = wid >> 2;
    const int m0 = blockIdx.y * 128, n0 = blockIdx.x * 128;
    const uint32_t sb = smem_u32(sm);

    load_tile_f32<256>(X, (size_t)m0, EE, 0, sm + 0,     128, tid);
    load_tile_f32<256>(W, (size_t)n0, EE, 0, sm + 16384, 128, tid);
    __syncthreads();

    float c[2][8][4] = {};

    for (int chunk = 0; chunk < 8; chunk++) {
        const uint32_t cur = (chunk & 1) * 32768;
        uint2 pa[8], pb[8];
        if (chunk < 7) {
            const int k0 = (chunk + 1) * 64;
            pf_ld128fc(X, (size_t)m0, EE, k0, pa, tid);
            pf_ld128fc(W, (size_t)n0, EE, k0, pb, tid);
        }
#pragma unroll
        for (int kk = 0; kk < 4; kk++) {
            uint32_t af[2][4];
            ldsm4(af[0], addrA(sb + cur + 0, 32*wm,      kk*32, lane));
            ldsm4(af[1], addrA(sb + cur + 0, 32*wm + 16, kk*32, lane));
#pragma unroll
            for (int t = 0; t < 4; t++) {
                uint32_t bh[4];
                ldsm4(bh, addrB(sb + cur + 16384, 64*wn + 16*t, kk*32, lane));
#pragma unroll
                for (int mt = 0; mt < 2; mt++) {
                    mma_f16(c[mt][2*t],   af[mt], bh);
                    mma_f16(c[mt][2*t+1], af[mt], bh + 2);
                }
            }
        }
        if (chunk < 7) {
            const uint32_t oth = ((chunk + 1) & 1) * 32768;
            pf_st128c(pa, sm + oth + 0,     tid);
            pf_st128c(pb, sm + oth + 16384, tid);
        }
        __syncthreads();
    }

    const int g = lane >> 2, tig = lane & 3;
    if (z != 2) {
        // Q/K: [B,H,N,D], half2 stores
#pragma unroll
        for (int mt = 0; mt < 2; mt++) {
#pragma unroll
            for (int t = 0; t < 8; t++) {
                const int e = n0 + 64*wn + 8*t + 2*tig;
                const float bv0 = bias[e], bv1 = bias[e + 1];
#pragma unroll
                for (int hf = 0; hf < 2; hf++) {
                    const int m = m0 + 32*wm + 16*mt + g + 8*hf;
                    const float v0 = (c[mt][t][2*hf] + bv0) * oscale;
                    const float v1 = (c[mt][t][2*hf + 1] + bv1) * oscale;
                    const int bb = m >> 12, nn = m & (NN - 1);
                    const int hh = e >> 6, d = e & 63;
                    size_t idx = (((size_t)bb*HH + hh)*NN + nn)*DD + d;
                    *reinterpret_cast<uint32_t*>(Oh + idx) = pack_f16(v0, v1);
                }
            }
        }
    } else {
        // V: stage through smem (free after mainloop), emit coalesced [B,H,D,N] rows
        __half* st = reinterpret_cast<__half*>(sm);     // [128 e][136 pad] halves = 34.8KB
#pragma unroll
        for (int mt = 0; mt < 2; mt++) {
#pragma unroll
            for (int t = 0; t < 8; t++) {
                const int el = 64*wn + 8*t + 2*tig;
                const float bv0 = bias[n0 + el], bv1 = bias[n0 + el + 1];
#pragma unroll
                for (int hf = 0; hf < 2; hf++) {
                    const int ml = 32*wm + 16*mt + g + 8*hf;
                    st[el * 136 + ml]       = __float2half_rn(c[mt][t][2*hf] + bv0);
                    st[(el + 1) * 136 + ml] = __float2half_rn(c[mt][t][2*hf + 1] + bv1);
                }
            }
        }
        __syncthreads();
        const int bb = m0 >> 12;
        const int nbase = m0 & (NN - 1);
#pragma unroll
        for (int j = 0; j < 8; j++) {
            int i = tid + j * 256;          // 0..2047
            int r = i >> 4, cc = i & 15;    // e row, 8-half chunk
            uint4 val = *reinterpret_cast<const uint4*>(st + r * 136 + cc * 8);
            const int eg = n0 + r;
            const int hh = eg >> 6, d = eg & 63;
            *reinterpret_cast<uint4*>(Oh + (((size_t)bb*HH + hh)*DD + d)*NN + nbase + cc*8) = val;
        }
    }
}

// ---------------- output projection, 128x128 tiles, double-buffered, 1 sync/chunk ----------------
__global__ void __launch_bounds__(256, 2) gemm_o(
    const __half* __restrict__ A16, const float* __restrict__ W,
    const float* __restrict__ bias, float* __restrict__ Of)
{
    extern __shared__ char sm[];
    const int tid = threadIdx.x, lane = tid & 31, wid = tid >> 5;
    const int wm = wid & 3, wn = wid >> 2;
    const int m0 = blockIdx.y * 128, n0 = blockIdx.x * 128;
    const uint32_t sb = smem_u32(sm);

    load_tile<256>(A16, (size_t)m0, EE, 0, sm + 0,     128, tid);
    load_tile_f32<256>(W, (size_t)n0, EE, 0, sm + 16384, 128, tid);
    __syncthreads();

    float c[2][8][4] = {};

    for (int chunk = 0; chunk < 8; chunk++) {
        const uint32_t cur = (chunk & 1) * 32768;
        uint4 pa[4]; uint2 pb[8];
        if (chunk < 7) {
            const int k0 = (chunk + 1) * 64;
            pf_ld128h(A16, (size_t)m0, EE, k0, pa, tid);
            pf_ld128fc(W, (size_t)n0, EE, k0, pb, tid);
        }
#pragma unroll
        for (int kk = 0; kk < 4; kk++) {
            uint32_t af[2][4];
            ldsm4(af[0], addrA(sb + cur + 0, 32*wm,      kk*32, lane));
            ldsm4(af[1], addrA(sb + cur + 0, 32*wm + 16, kk*32, lane));
#pragma unroll
            for (int t = 0; t < 4; t++) {
                uint32_t bh[4];
                ldsm4(bh, addrB(sb + cur + 16384, 64*wn + 16*t, kk*32, lane));
#pragma unroll
                for (int mt = 0; mt < 2; mt++) {
                    mma_f16(c[mt][2*t],   af[mt], bh);
                    mma_f16(c[mt][2*t+1], af[mt], bh + 2);
                }
            }
        }
        if (chunk < 7) {
            const uint32_t oth = ((chunk + 1) & 1) * 32768;
            pf_st128h(pa, sm + oth + 0,     tid);
            pf_st128c(pb, sm + oth + 16384, tid);
        }
        __syncthreads();
    }

    const int g = lane >> 2, tig = lane & 3;
#pragma unroll
    for (int mt = 0; mt < 2; mt++) {
#pragma unroll
        for (int t = 0; t < 8; t++) {
            const int e = n0 + 64*wn + 8*t + 2*tig;
            const float bv0 = bias[e], bv1 = bias[e + 1];
#pragma unroll
            for (int hf = 0; hf < 2; hf++) {
                const int m = m0 + 32*wm + 16*mt + g + 8*hf;
                *reinterpret_cast<float2*>(Of + (size_t)m * EE + e) =
                    make_float2(c[mt][t][2*hf] + bv0, c[mt][t][2*hf + 1] + bv1);
            }
        }
    }
}

// ---------------- flash attention (round-11 config): 128 q-rows, 2 CTAs/SM, pipelined softmax ----------------
// CTA = 128 q-rows of one (b,h); 4 warps x 32 q-rows; 64-key tiles; 1 sync/tile.
#define A_QH 0
#define A_KV0 16384        // stage s at A_KV0 + s*16384: K (8KB) then V (8KB)
#define A_SMEM 49152

__global__ void __launch_bounds__(128, 2) attn_mma(
    const __half* __restrict__ qp, const __half* __restrict__ kp,
    const __half* __restrict__ vt, __half* __restrict__ att)
{
    extern __shared__ char sm[];
    const int tid = threadIdx.x, lane = tid & 31, wid = tid >> 5;
    const int b = blockIdx.z, h = blockIdx.y, i0 = blockIdx.x * 128;
    const int bh = b * HH + h;
    const uint32_t sb = smem_u32(sm);

    load_tile<128>(qp, (size_t)bh * NN + i0, DD, 0, sm + A_QH, 128, tid);
    load_tile<128>(kp, (size_t)bh * NN, DD, 0, sm + A_KV0, 64, tid);
    load_tile<128>(vt, (size_t)bh * DD, NN, 0, sm + A_KV0 + 8192, 64, tid);
    __syncthreads();

    // Q fragments hoisted: constant across all key tiles
    uint32_t qf[4][2][4];
#pragma unroll
    for (int kk = 0; kk < 4; kk++) {
        ldsm4(qf[kk][0], addrA(sb + A_QH, 32*wid,      kk*32, lane));
        ldsm4(qf[kk][1], addrA(sb + A_QH, 32*wid + 16, kk*32, lane));
    }

    float o[2][8][4] = {};
    float lsum[2][2] = {};

    for (int t = 0; t < 64; t++) {
        const uint32_t bK = sb + A_KV0 + (t & 1) * 16384;
        const uint32_t bV = bK + 8192;
        char* nxt = sm + A_KV0 + ((t + 1) & 1) * 16384;

        uint4 kreg[4], vreg[4];
        if (t < 63) {
            pf_ld64s(kp, (size_t)bh * NN + (t + 1) * 64, DD, 0, kreg, tid);
            pf_ld64s(vt, (size_t)bh * DD, NN, (t + 1) * 64, vreg, tid);
        }

        float c[2][8][4] = {};

        // exp + PV for key-slice j (16 keys): runs under S(j+1)'s MMA latency
        auto exp_pv = [&](int j) {
            uint32_t ah[2][4];
#pragma unroll
            for (int mt = 0; mt < 2; mt++) {
                uint32_t a01a = h2ex2(pack_f16(c[mt][2*j][0],   c[mt][2*j][1]));
                uint32_t a23a = h2ex2(pack_f16(c[mt][2*j][2],   c[mt][2*j][3]));
                uint32_t a01b = h2ex2(pack_f16(c[mt][2*j+1][0], c[mt][2*j+1][1]));
                uint32_t a23b = h2ex2(pack_f16(c[mt][2*j+1][2], c[mt][2*j+1][3]));
                ah[mt][0] = a01a; ah[mt][1] = a23a; ah[mt][2] = a01b; ah[mt][3] = a23b;
                float2 f01 = h2f2(hadd2(a01a, a01b));
                float2 f23 = h2f2(hadd2(a23a, a23b));
                lsum[mt][0] += f01.x + f01.y;
                lsum[mt][1] += f23.x + f23.y;
            }
#pragma unroll
            for (int tv = 0; tv < 4; tv++) {
                uint32_t vh[4];
                ldsm4(vh, addrB(bV, 16*tv, j*32, lane));
#pragma unroll
                for (int mt = 0; mt < 2; mt++) {
                    mma_f16(o[mt][2*tv],   ah[mt], vh);
                    mma_f16(o[mt][2*tv+1], ah[mt], vh + 2);
                }
            }
        };

#pragma unroll
        for (int tt = 0; tt < 4; tt++) {
#pragma unroll
            for (int kk = 0; kk < 4; kk++) {
                uint32_t bhf[4];
                ldsm4(bhf, addrB(bK, 16*tt, kk*32, lane));
#pragma unroll
                for (int mt = 0; mt < 2; mt++) {
                    mma_f16(c[mt][2*tt],   qf[kk][mt], bhf);
                    mma_f16(c[mt][2*tt+1], qf[kk][mt], bhf + 2);
                }
            }
            if (tt > 0) exp_pv(tt - 1);
        }
        exp_pv(3);

        if (t < 63) {
            pf_st64s(kreg, nxt, tid);
            pf_st64s(vreg, nxt + 8192, tid);
        }
        __syncthreads();
    }

    // ---- reduce row sums across the 4 tig lanes, normalize, write fp16 ----
#pragma unroll
    for (int mt = 0; mt < 2; mt++)
#pragma unroll
        for (int hf = 0; hf < 2; hf++) {
            float s = lsum[mt][hf];
            s += __shfl_xor_sync(0xffffffffu, s, 1);
            s += __shfl_xor_sync(0xffffffffu, s, 2);
            lsum[mt][hf] = 1.0f / s;
        }

    const int g = lane >> 2, tig = lane & 3;
#pragma unroll
    for (int mt = 0; mt < 2; mt++) {
#pragma unroll
        for (int nt = 0; nt < 8; nt++) {
            const int d = 8*nt + 2*tig;
#pragma unroll
            for (int hf = 0; hf < 2; hf++) {
                const float inv = lsum[mt][hf];
                const int row = i0 + 32*wid + 16*mt + g + 8*hf;
                const size_t idx = ((size_t)b * NN + row) * EE + h * DD + d;
                *reinterpret_cast<uint32_t*>(att + idx) =
                    pack_f16(o[mt][nt][2*hf] * inv, o[mt][nt][2*hf + 1] * inv);
            }
        }
    }
}

// ---------------- host ----------------
extern "C" void kernel_launch(void* const* d_in, const int* in_sizes, int n_in,
                              void* d_out, int out_size)
{
    const float* q  = (const float*)d_in[0];
    const float* k  = (const float*)d_in[1];
    const float* v  = (const float*)d_in[2];
    const float* Wq = (const float*)d_in[3];
    const float* bq = (const float*)d_in[4];
    const float* Wk = (const float*)d_in[5];
    const float* bk = (const float*)d_in[6];
    const float* Wv = (const float*)d_in[7];
    const float* bv = (const float*)d_in[8];
    const float* Wo = (const float*)d_in[9];
    const float* bo = (const float*)d_in[10];
    float* out = (float*)d_out;

    __half* s;
    cudaGetSymbolAddress((void**)&s, g_scratch);
    __half *qp  = s,
           *kp  = s + (size_t)E1,
           *vtp = s + 2*(size_t)E1,
           *att = s + 3*(size_t)E1;

    cudaFuncSetAttribute(gemm_qkv, cudaFuncAttributeMaxDynamicSharedMemorySize, G_SMEM);
    cudaFuncSetAttribute(gemm_o,   cudaFuncAttributeMaxDynamicSharedMemorySize, G_SMEM);
    cudaFuncSetAttribute(attn_mma, cudaFuncAttributeMaxDynamicSharedMemorySize, A_SMEM);

    gemm_qkv<<<dim3(EE/128, MMR/128, 3), 256, G_SMEM>>>(
        q, k, v, Wq, Wk, Wv, bq, bk, bv, qp, kp, vtp);

    attn_mma<<<dim3(NN/128, HH, BB), 128, A_SMEM>>>(qp, kp, vtp, att);

    gemm_o<<<dim3(EE/128, MMR/128), 256, G_SMEM>>>(att, Wo, bo, out);
}